// round 7
// baseline (speedup 1.0000x reference)
#include <cuda_runtime.h>
#include <cstdint>

// ---------------------------------------------------------------------------
// MoE, sm_103: tf32 mma.sync + producer/consumer warp specialization.
//   out[t,o] = sum_e softmax_e(x@Wg+bg)_e * gelu(x@We[e] + be[e])
// B*T=16384, D=256, O=256, E=16.
//
// moe_kernel: CTA = 64 tokens x 128 cols, all 16 experts. 5 warps:
//   warps 0-3 compute (2Mx2N, warp tile 32x64, mma.m16n8k8.tf32, register
//   prefetch double-buffering), warp 4 producer (cp.async -> 3-stage ring).
//   2 CTAs/SM. No __syncthreads in the mainloop.
// ---------------------------------------------------------------------------

#define NTOK   16384
#define DD     256
#define OO     256
#define EE     16
#define TILE_M 64
#define TILE_N 128
#define NTHREADS 160          // 4 compute warps + 1 producer warp
#define NBUF   3

// smem layout (bytes)
#define SM_A      0                      // [wm2][kc8][ks4][mi2][lane32][16B]
#define SM_A_SIZE 65536
#define SM_B      65536                  // 3 x 16KB ring
#define SM_B_BUF  16384
#define SM_BAR    (SM_B + NBUF * SM_B_BUF)
#define MB_FULL(i)  (SM_BAR + (i) * 8)
#define MB_EMPTY(i) (SM_BAR + 24 + (i) * 8)
#define SMEM_TOTAL  (SM_BAR + 64)        // 114752 B -> 2 CTAs/SM (fits, r6)

// scratch: We in mma-fragment order for 32x64 warp tiles, tf32-rounded.
// idx bits: e(4)|ct(1)|kc(3)|wn(1)|ks(2)|p(2)|lane(5)  (float4 units)
__device__ float g_WeB[EE * DD * OO];
__device__ float g_gate[NTOK * EE];

// ---------------------------------------------------------------------------
__device__ __forceinline__ float tf32_rn(float x) {
    uint32_t u;
    asm("cvt.rna.tf32.f32 %0, %1;" : "=r"(u) : "f"(x));
    return __uint_as_float(u);
}
__device__ __forceinline__ uint32_t smem_u32(const void* p) {
    uint32_t a;
    asm("{ .reg .u64 t; cvta.to.shared.u64 t, %1; cvt.u32.u64 %0, t; }"
        : "=r"(a) : "l"(p));
    return a;
}
__device__ __forceinline__ void mma_tf32(float* c, const float4& a,
                                         float b0, float b1) {
    asm volatile(
        "mma.sync.aligned.m16n8k8.row.col.f32.tf32.tf32.f32 "
        "{%0,%1,%2,%3}, {%4,%5,%6,%7}, {%8,%9}, {%0,%1,%2,%3};\n"
        : "+f"(c[0]), "+f"(c[1]), "+f"(c[2]), "+f"(c[3])
        : "r"(__float_as_uint(a.x)), "r"(__float_as_uint(a.y)),
          "r"(__float_as_uint(a.z)), "r"(__float_as_uint(a.w)),
          "r"(__float_as_uint(b0)), "r"(__float_as_uint(b1)));
}
__device__ __forceinline__ void cp_async16(uint32_t saddr, const void* gaddr) {
    asm volatile("cp.async.cg.shared.global [%0], [%1], 16;\n"
                 :: "r"(saddr), "l"(gaddr));
}
__device__ __forceinline__ float gelu_exact(float v) {
    return 0.5f * v * (1.0f + erff(v * 0.70710678118654752440f));
}

#define MBAR_INIT(a, n) \
    asm volatile("mbarrier.init.shared.b64 [%0], %1;" :: "r"(a), "r"((uint32_t)(n)) : "memory")
#define MBAR_ARRIVE(a) \
    asm volatile("mbarrier.arrive.shared.b64 _, [%0];" :: "r"(a) : "memory")
#define MBAR_WAIT(a, ph) do {                                                 \
    asm volatile("{\n\t.reg .pred P1;\n\t"                                    \
        "WL_%=:\n\tmbarrier.try_wait.parity.acquire.cta.shared::cta.b64 P1, [%0], %1, 0x989680;\n\t" \
        "@P1 bra.uni WD_%=;\n\tbra.uni WL_%=;\n\tWD_%=:\n\t}"                 \
        :: "r"(a), "r"((uint32_t)(ph)) : "memory");                           \
} while (0)
#define CP_ARRIVE_NOINC(a) \
    asm volatile("cp.async.mbarrier.arrive.noinc.shared::cta.b64 [%0];" :: "r"(a) : "memory")
#define NAMED_BAR(id, n) \
    asm volatile("bar.sync %0, %1;" :: "r"(id), "r"(n) : "memory")

// ---------------------------------------------------------------------------
// Pre-pass: permute We[e][d][o] into 32x64-warp-tile fragment order.
// ---------------------------------------------------------------------------
__global__ void permute_we(const float* __restrict__ We) {
    int idx = blockIdx.x * blockDim.x + threadIdx.x;   // 0 .. 262143
    int lane = idx & 31;
    int p    = (idx >> 5) & 3;
    int ks   = (idx >> 7) & 3;
    int wn   = (idx >> 9) & 1;
    int kc   = (idx >> 10) & 7;
    int ct   = (idx >> 13) & 1;
    int e    = idx >> 14;
    int d0 = kc * 32 + ks * 8 + (lane & 3);
    int o0 = ct * 128 + wn * 64 + p * 16 + (lane >> 2);
    const float* w = We + (size_t)e * DD * OO;
    float4 v;
    v.x = tf32_rn(w[(size_t)d0 * OO + o0]);
    v.y = tf32_rn(w[(size_t)(d0 + 4) * OO + o0]);
    v.z = tf32_rn(w[(size_t)d0 * OO + o0 + 8]);
    v.w = tf32_rn(w[(size_t)(d0 + 4) * OO + o0 + 8]);
    *reinterpret_cast<float4*>(g_WeB + (size_t)idx * 4) = v;
}

// ---------------------------------------------------------------------------
// Main kernel.
// ---------------------------------------------------------------------------
__global__ __launch_bounds__(NTHREADS, 2)
void moe_kernel(const float* __restrict__ x, const float* __restrict__ be,
                const float* __restrict__ Wg, const float* __restrict__ bg,
                float* __restrict__ out) {
    extern __shared__ float smf[];
    char* smc = reinterpret_cast<char*>(smf);
    const uint32_t sbase = smem_u32(smc);
    const int tid  = threadIdx.x;
    const int wid  = tid >> 5;
    const int lane = tid & 31;
    const int token0 = (blockIdx.x >> 1) * TILE_M;
    const int ct     = blockIdx.x & 1;
    const int col0   = ct * TILE_N;

    if (tid == 0) {
        #pragma unroll
        for (int i = 0; i < NBUF; i++) {
            MBAR_INIT(sbase + MB_FULL(i), 32);   // cp.async noinc
            MBAR_INIT(sbase + MB_EMPTY(i), 4);   // one per compute warp
        }
    }
    __syncthreads();

    if (wid == 4) {
        // ================= producer warp =================
        int ph_e[NBUF];
        #pragma unroll
        for (int i = 0; i < NBUF; i++) ph_e[i] = 0;
        int buf = 0;
        #pragma unroll 1
        for (int c = 0; c < EE * 8; c++) {
            if (c >= NBUF) { MBAR_WAIT(sbase + MB_EMPTY(buf), ph_e[buf]); }
            if (c >= NBUF && buf == NBUF - 1) {
                ph_e[0] ^= 1; ph_e[1] ^= 1; ph_e[2] ^= 1;
            }
            const int e = c >> 3, kc = c & 7;
            const char* gsrc = reinterpret_cast<const char*>(
                g_WeB + (size_t)(e * 16 + ct * 8 + kc) * 4096) + lane * 16;
            const uint32_t dst = sbase + SM_B + (uint32_t)buf * SM_B_BUF
                               + (uint32_t)lane * 16;
            #pragma unroll
            for (int i = 0; i < 32; i++)
                cp_async16(dst + i * 512, gsrc + i * 512);
            CP_ARRIVE_NOINC(sbase + MB_FULL(buf));
            buf = (buf == NBUF - 1) ? 0 : buf + 1;
        }
    } else {
        // ================= compute warps =================
        const int wm = wid & 1;          // M half (32 tokens)
        const int wn = wid >> 1;         // N half (64 cols)

        // ---- build A_perm (fragment-order x, tf32) -------------------
        {
            #pragma unroll
            for (int it = 0; it < 32; it++) {
                int idx = tid + (it << 7);         // 0..4095 float4 slots
                int ln = idx & 31;
                int mi = (idx >> 5) & 1;
                int ks = (idx >> 6) & 3;
                int kc = (idx >> 8) & 7;
                int wmm = idx >> 11;
                int r = ln >> 2, cc = ln & 3;
                int row = token0 + wmm * 32 + mi * 16 + r;
                int d = kc * 32 + ks * 8 + cc;
                const float* xp = x + (size_t)row * DD + d;
                float4 v;
                v.x = tf32_rn(xp[0]);
                v.y = tf32_rn(xp[8 * DD]);
                v.z = tf32_rn(xp[4]);
                v.w = tf32_rn(xp[8 * DD + 4]);
                *reinterpret_cast<float4*>(smc + SM_A + (size_t)idx * 16) = v;
            }
        }
        // ---- gate: softmax(x@Wg+bg), token = tid>>1, experts 8*(tid&1)
        {
            const int tok = tid >> 1;
            const int qh  = tid & 1;           // expert half
            float acc[8];
            #pragma unroll
            for (int j = 0; j < 8; j++) acc[j] = 0.0f;
            const float4* x4 = reinterpret_cast<const float4*>(
                x + (size_t)(token0 + tok) * DD);
            const float4* wg4 = reinterpret_cast<const float4*>(Wg);
            #pragma unroll 4
            for (int d4 = 0; d4 < 64; d4++) {
                float4 xv = x4[d4];
                const float* xvp = &xv.x;
                #pragma unroll
                for (int dd = 0; dd < 4; dd++) {
                    int d = d4 * 4 + dd;
                    float4 wA = wg4[d * 4 + qh * 2];
                    float4 wB = wg4[d * 4 + qh * 2 + 1];
                    float xs = xvp[dd];
                    acc[0] += xs * wA.x; acc[1] += xs * wA.y;
                    acc[2] += xs * wA.z; acc[3] += xs * wA.w;
                    acc[4] += xs * wB.x; acc[5] += xs * wB.y;
                    acc[6] += xs * wB.z; acc[7] += xs * wB.w;
                }
            }
            #pragma unroll
            for (int j = 0; j < 8; j++) acc[j] += __ldg(bg + qh * 8 + j);
            float m = acc[0];
            #pragma unroll
            for (int j = 1; j < 8; j++) m = fmaxf(m, acc[j]);
            m = fmaxf(m, __shfl_xor_sync(0xFFFFFFFFu, m, 1));
            float s = 0.0f;
            #pragma unroll
            for (int j = 0; j < 8; j++) { acc[j] = __expf(acc[j] - m); s += acc[j]; }
            s += __shfl_xor_sync(0xFFFFFFFFu, s, 1);
            float inv = 1.0f / s;
            float4 g0 = make_float4(acc[0] * inv, acc[1] * inv, acc[2] * inv, acc[3] * inv);
            float4 g1 = make_float4(acc[4] * inv, acc[5] * inv, acc[6] * inv, acc[7] * inv);
            float* gp = g_gate + (size_t)(token0 + tok) * EE + qh * 8;
            *reinterpret_cast<float4*>(gp) = g0;
            *reinterpret_cast<float4*>(gp + 4) = g1;
        }
        NAMED_BAR(1, 128);     // compute warps: A + gate ready

        float oacc[2][8][4];
        #pragma unroll
        for (int mi = 0; mi < 2; mi++)
            #pragma unroll
            for (int j = 0; j < 8; j++)
                #pragma unroll
                for (int q = 0; q < 4; q++) oacc[mi][j][q] = 0.0f;

        int ph_f[NBUF];
        #pragma unroll
        for (int i = 0; i < NBUF; i++) ph_f[i] = 0;
        int buf = 0;

        #pragma unroll 1
        for (int e = 0; e < EE; e++) {
            float hacc[2][8][4];
            #pragma unroll
            for (int mi = 0; mi < 2; mi++)
                #pragma unroll
                for (int j = 0; j < 8; j++)
                    #pragma unroll
                    for (int q = 0; q < 4; q++) hacc[mi][j][q] = 0.0f;

            #pragma unroll 1
            for (int kc = 0; kc < 8; kc++) {
                MBAR_WAIT(sbase + MB_FULL(buf), ph_f[buf]);
                ph_f[buf] ^= 1;

                const char* bb = smc + SM_B + buf * SM_B_BUF;
                const char* ab = smc + SM_A + ((wm * 8 + kc) * 4) * 1024;

                // prefetch ks=0 fragments
                float4 a0 = *reinterpret_cast<const float4*>(ab + lane * 16);
                float4 a1 = *reinterpret_cast<const float4*>(ab + 512 + lane * 16);
                float4 b0f = *reinterpret_cast<const float4*>(bb + (wn * 16 + 0) * 512 + lane * 16);
                float4 b1f = *reinterpret_cast<const float4*>(bb + (wn * 16 + 1) * 512 + lane * 16);
                float4 b2f = *reinterpret_cast<const float4*>(bb + (wn * 16 + 2) * 512 + lane * 16);
                float4 b3f = *reinterpret_cast<const float4*>(bb + (wn * 16 + 3) * 512 + lane * 16);

                #pragma unroll
                for (int ks = 0; ks < 4; ks++) {
                    float4 na0, na1, nb0, nb1, nb2, nb3;
                    if (ks < 3) {
                        const char* abn = ab + (ks + 1) * 1024;
                        const char* bbn = bb + (wn * 16 + (ks + 1) * 4) * 512;
                        na0 = *reinterpret_cast<const float4*>(abn + lane * 16);
                        na1 = *reinterpret_cast<const float4*>(abn + 512 + lane * 16);
                        nb0 = *reinterpret_cast<const float4*>(bbn + lane * 16);
                        nb1 = *reinterpret_cast<const float4*>(bbn + 512 + lane * 16);
                        nb2 = *reinterpret_cast<const float4*>(bbn + 1024 + lane * 16);
                        nb3 = *reinterpret_cast<const float4*>(bbn + 1536 + lane * 16);
                    }
                    mma_tf32(hacc[0][0], a0, b0f.x, b0f.y);
                    mma_tf32(hacc[1][0], a1, b0f.x, b0f.y);
                    mma_tf32(hacc[0][1], a0, b0f.z, b0f.w);
                    mma_tf32(hacc[1][1], a1, b0f.z, b0f.w);
                    mma_tf32(hacc[0][2], a0, b1f.x, b1f.y);
                    mma_tf32(hacc[1][2], a1, b1f.x, b1f.y);
                    mma_tf32(hacc[0][3], a0, b1f.z, b1f.w);
                    mma_tf32(hacc[1][3], a1, b1f.z, b1f.w);
                    mma_tf32(hacc[0][4], a0, b2f.x, b2f.y);
                    mma_tf32(hacc[1][4], a1, b2f.x, b2f.y);
                    mma_tf32(hacc[0][5], a0, b2f.z, b2f.w);
                    mma_tf32(hacc[1][5], a1, b2f.z, b2f.w);
                    mma_tf32(hacc[0][6], a0, b3f.x, b3f.y);
                    mma_tf32(hacc[1][6], a1, b3f.x, b3f.y);
                    mma_tf32(hacc[0][7], a0, b3f.z, b3f.w);
                    mma_tf32(hacc[1][7], a1, b3f.z, b3f.w);
                    if (ks < 3) {
                        a0 = na0; a1 = na1;
                        b0f = nb0; b1f = nb1; b2f = nb2; b3f = nb3;
                    }
                }
                if (lane == 0) MBAR_ARRIVE(sbase + MB_EMPTY(buf));
                buf = (buf == NBUF - 1) ? 0 : buf + 1;
            }

            // epilogue: bias + exact gelu + gate-weighted accumulate
            #pragma unroll
            for (int mi = 0; mi < 2; mi++) {
                int rr = token0 + wm * 32 + mi * 16 + (lane >> 2);
                float g0 = __ldg(g_gate + (size_t)rr * EE + e);
                float g1 = __ldg(g_gate + (size_t)(rr + 8) * EE + e);
                #pragma unroll
                for (int j = 0; j < 8; j++) {
                    int n0 = col0 + wn * 64 + j * 8 + (lane & 3) * 2;
                    float bv0 = __ldg(be + (size_t)e * OO + n0);
                    float bv1 = __ldg(be + (size_t)e * OO + n0 + 1);
                    oacc[mi][j][0] = fmaf(g0, gelu_exact(hacc[mi][j][0] + bv0), oacc[mi][j][0]);
                    oacc[mi][j][1] = fmaf(g0, gelu_exact(hacc[mi][j][1] + bv1), oacc[mi][j][1]);
                    oacc[mi][j][2] = fmaf(g1, gelu_exact(hacc[mi][j][2] + bv0), oacc[mi][j][2]);
                    oacc[mi][j][3] = fmaf(g1, gelu_exact(hacc[mi][j][3] + bv1), oacc[mi][j][3]);
                }
            }
        }

        // ---- store ----
        #pragma unroll
        for (int mi = 0; mi < 2; mi++) {
            int row = token0 + wm * 32 + mi * 16 + (lane >> 2);
            #pragma unroll
            for (int j = 0; j < 8; j++) {
                int n = col0 + wn * 64 + j * 8 + (lane & 3) * 2;
                float2 v0 = make_float2(oacc[mi][j][0], oacc[mi][j][1]);
                float2 v1 = make_float2(oacc[mi][j][2], oacc[mi][j][3]);
                *reinterpret_cast<float2*>(out + (size_t)row * OO + n) = v0;
                *reinterpret_cast<float2*>(out + (size_t)(row + 8) * OO + n) = v1;
            }
        }
    }
}

// ---------------------------------------------------------------------------
// kernel_launch — graph-capturable, allocation-free.
// Inputs: x[4,4096,256] f32, We[16,256,256] f32, be[16,256] f32,
//         Wg[256,16] f32, bg[16] f32. Output: [4,4096,256] f32.
// ---------------------------------------------------------------------------
extern "C" void kernel_launch(void* const* d_in, const int* in_sizes, int n_in,
                              void* d_out, int out_size) {
    const float* x  = (const float*)d_in[0];
    const float* We = (const float*)d_in[1];
    const float* be = (const float*)d_in[2];
    const float* Wg = (const float*)d_in[3];
    const float* bg = (const float*)d_in[4];
    float* out = (float*)d_out;

    cudaFuncSetAttribute(moe_kernel,
                         cudaFuncAttributeMaxDynamicSharedMemorySize, SMEM_TOTAL);

    permute_we<<<1024, 256>>>(We);
    moe_kernel<<<(NTOK / TILE_M) * 2, NTHREADS, SMEM_TOTAL>>>(x, be, Wg, bg, out);
}

// round 8
// speedup vs baseline: 1.1306x; 1.1306x over previous
#include <cuda_runtime.h>
#include <cstdint>

// ---------------------------------------------------------------------------
// MoE, sm_103: tf32 mma.sync + producer/consumer warp specialization.
//   out[t,o] = sum_e softmax_e(x@Wg+bg)_e * gelu(x@We[e] + be[e])
// B*T=16384, D=256, O=256, E=16.
//
// moe_kernel: CTA = 128 tokens x 128 cols (1 CTA/SM), all 16 experts.
//   18 warps: 16 compute (4Mx4N, warp tile 32x32, mma.m16n8k8.tf32),
//   2 producer (cp.async -> 4-stage 16KB mbarrier ring).
//   No __syncthreads in the mainloop. Gate softmax fused into prologue.
// ---------------------------------------------------------------------------

#define NTOK   16384
#define DD     256
#define OO     256
#define EE     16
#define TILE_M 128
#define TILE_N 128
#define NTHREADS 576          // 16 compute warps + 2 producer warps
#define NBUF   4

// smem layout (bytes)
#define SM_A      0                      // [wm4][kc8][ks4][mi2][lane32][16B]
#define SM_A_SIZE 131072
#define SM_B      131072                 // 4 x 16KB ring
#define SM_B_BUF  16384
#define SM_BAR    (SM_B + NBUF * SM_B_BUF)
#define MB_FULL(i)  (SM_BAR + (i) * 8)
#define MB_EMPTY(i) (SM_BAR + 32 + (i) * 8)
#define SMEM_TOTAL  (SM_BAR + 96)        // 196704 B -> 1 CTA/SM

// scratch: We in mma-fragment order (32x32 warp tiles), tf32-rounded.
// idx bits: e(4)|ct(1)|kc(3)|wn(2)|ks(2)|p(1)|lane(5)  (float4 units)
__device__ float g_WeB[EE * DD * OO];
__device__ float g_gate[NTOK * EE];

// ---------------------------------------------------------------------------
__device__ __forceinline__ float tf32_rn(float x) {
    uint32_t u;
    asm("cvt.rna.tf32.f32 %0, %1;" : "=r"(u) : "f"(x));
    return __uint_as_float(u);
}
__device__ __forceinline__ uint32_t smem_u32(const void* p) {
    uint32_t a;
    asm("{ .reg .u64 t; cvta.to.shared.u64 t, %1; cvt.u32.u64 %0, t; }"
        : "=r"(a) : "l"(p));
    return a;
}
__device__ __forceinline__ void mma_tf32(float* c, const float4& a,
                                         float b0, float b1) {
    asm volatile(
        "mma.sync.aligned.m16n8k8.row.col.f32.tf32.tf32.f32 "
        "{%0,%1,%2,%3}, {%4,%5,%6,%7}, {%8,%9}, {%0,%1,%2,%3};\n"
        : "+f"(c[0]), "+f"(c[1]), "+f"(c[2]), "+f"(c[3])
        : "r"(__float_as_uint(a.x)), "r"(__float_as_uint(a.y)),
          "r"(__float_as_uint(a.z)), "r"(__float_as_uint(a.w)),
          "r"(__float_as_uint(b0)), "r"(__float_as_uint(b1)));
}
__device__ __forceinline__ void cp_async16(uint32_t saddr, const void* gaddr) {
    asm volatile("cp.async.cg.shared.global [%0], [%1], 16;\n"
                 :: "r"(saddr), "l"(gaddr));
}
__device__ __forceinline__ float gelu_exact(float v) {
    return 0.5f * v * (1.0f + erff(v * 0.70710678118654752440f));
}

#define MBAR_INIT(a, n) \
    asm volatile("mbarrier.init.shared.b64 [%0], %1;" :: "r"(a), "r"((uint32_t)(n)) : "memory")
#define MBAR_ARRIVE(a) \
    asm volatile("mbarrier.arrive.shared.b64 _, [%0];" :: "r"(a) : "memory")
#define MBAR_WAIT(a, ph) do {                                                 \
    asm volatile("{\n\t.reg .pred P1;\n\t"                                    \
        "WL_%=:\n\tmbarrier.try_wait.parity.acquire.cta.shared::cta.b64 P1, [%0], %1, 0x989680;\n\t" \
        "@P1 bra.uni WD_%=;\n\tbra.uni WL_%=;\n\tWD_%=:\n\t}"                 \
        :: "r"(a), "r"((uint32_t)(ph)) : "memory");                           \
} while (0)
#define CP_ARRIVE_NOINC(a) \
    asm volatile("cp.async.mbarrier.arrive.noinc.shared::cta.b64 [%0];" :: "r"(a) : "memory")
#define NAMED_BAR(id, n) \
    asm volatile("bar.sync %0, %1;" :: "r"(id), "r"(n) : "memory")

// ---------------------------------------------------------------------------
// Pre-pass: permute We[e][d][o] into 32x32-warp-tile fragment order (as R6).
// ---------------------------------------------------------------------------
__global__ void permute_we(const float* __restrict__ We) {
    int idx = blockIdx.x * blockDim.x + threadIdx.x;   // 0 .. 262143
    int lane = idx & 31;
    int p    = (idx >> 5) & 1;
    int ks   = (idx >> 6) & 3;
    int wn   = (idx >> 8) & 3;
    int kc   = (idx >> 10) & 7;
    int ct   = (idx >> 13) & 1;
    int e    = idx >> 14;
    int d0 = kc * 32 + ks * 8 + (lane & 3);
    int o0 = ct * 128 + wn * 32 + (lane >> 2) + p * 16;
    const float* w = We + (size_t)e * DD * OO;
    float4 v;
    v.x = tf32_rn(w[(size_t)d0 * OO + o0]);
    v.y = tf32_rn(w[(size_t)(d0 + 4) * OO + o0]);
    v.z = tf32_rn(w[(size_t)d0 * OO + o0 + 8]);
    v.w = tf32_rn(w[(size_t)(d0 + 4) * OO + o0 + 8]);
    *reinterpret_cast<float4*>(g_WeB + (size_t)idx * 4) = v;
}

// ---------------------------------------------------------------------------
// Main kernel: 1 CTA/SM, 128x128 tile.
// ---------------------------------------------------------------------------
__global__ __launch_bounds__(NTHREADS, 1)
void moe_kernel(const float* __restrict__ x, const float* __restrict__ be,
                const float* __restrict__ Wg, const float* __restrict__ bg,
                float* __restrict__ out) {
    extern __shared__ float smf[];
    char* smc = reinterpret_cast<char*>(smf);
    const uint32_t sbase = smem_u32(smc);
    const int tid  = threadIdx.x;
    const int wid  = tid >> 5;
    const int lane = tid & 31;
    const int token0 = (blockIdx.x >> 1) * TILE_M;
    const int ct     = blockIdx.x & 1;
    const int col0   = ct * TILE_N;

    if (tid == 0) {
        #pragma unroll
        for (int i = 0; i < NBUF; i++) {
            MBAR_INIT(sbase + MB_FULL(i), 64);   // 64 producer threads, noinc
            MBAR_INIT(sbase + MB_EMPTY(i), 16);  // one arrive per compute warp
        }
    }
    __syncthreads();

    if (wid >= 16) {
        // ================= producer warps (2 x 32 threads) =================
        const int ltid = tid - 512;              // 0..63
        int ph_e[NBUF];
        #pragma unroll
        for (int i = 0; i < NBUF; i++) ph_e[i] = 0;
        #pragma unroll 1
        for (int c = 0; c < EE * 8; c++) {
            const int buf = c & (NBUF - 1);
            if (c >= NBUF) {
                MBAR_WAIT(sbase + MB_EMPTY(buf), ph_e[buf]);
                ph_e[buf] ^= 1;
            }
            const int e = c >> 3, kc = c & 7;
            const char* gsrc = reinterpret_cast<const char*>(
                g_WeB + (size_t)(e * 16 + ct * 8 + kc) * 4096) + ltid * 16;
            const uint32_t dst = sbase + SM_B + (uint32_t)buf * SM_B_BUF
                               + (uint32_t)ltid * 16;
            #pragma unroll
            for (int i = 0; i < 16; i++)
                cp_async16(dst + i * 1024, gsrc + i * 1024);
            CP_ARRIVE_NOINC(sbase + MB_FULL(buf));
        }
    } else {
        // ================= compute warps (16 x 32 threads) =================
        const int wm = wid & 3;          // 4 row groups of 32 tokens
        const int wn = wid >> 2;         // 4 col groups of 32 cols

        // ---- build A_perm (fragment-order x, tf32): 8192 float4 slots ----
        {
            #pragma unroll
            for (int it = 0; it < 16; it++) {
                int idx = tid + (it << 9);         // tid 0..511
                int ln = idx & 31;
                int mi = (idx >> 5) & 1;
                int ks = (idx >> 6) & 3;
                int kc = (idx >> 8) & 7;
                int wmm = idx >> 11;               // 0..3
                int r = ln >> 2, cc = ln & 3;
                int row = token0 + wmm * 32 + mi * 16 + r;
                int d = kc * 32 + ks * 8 + cc;
                const float* xp = x + (size_t)row * DD + d;
                float4 v;
                v.x = tf32_rn(xp[0]);
                v.y = tf32_rn(xp[8 * DD]);
                v.z = tf32_rn(xp[4]);
                v.w = tf32_rn(xp[8 * DD + 4]);
                *reinterpret_cast<float4*>(smc + SM_A + (size_t)idx * 16) = v;
            }
        }
        // ---- gate: softmax(x@Wg+bg). 4 threads/token, 4 experts each ----
        {
            const int tok = tid >> 2;          // 0..127
            const int q   = tid & 3;
            float acc0 = 0.f, acc1 = 0.f, acc2 = 0.f, acc3 = 0.f;
            const float4* x4 = reinterpret_cast<const float4*>(
                x + (size_t)(token0 + tok) * DD);
            const float4* wg4 = reinterpret_cast<const float4*>(Wg);
            #pragma unroll 4
            for (int d4 = 0; d4 < 64; d4++) {
                float4 xv = x4[d4];
                float4 w0 = wg4[(d4 * 4 + 0) * 4 + q];
                float4 w1 = wg4[(d4 * 4 + 1) * 4 + q];
                float4 w2 = wg4[(d4 * 4 + 2) * 4 + q];
                float4 w3 = wg4[(d4 * 4 + 3) * 4 + q];
                acc0 += xv.x * w0.x + xv.y * w1.x + xv.z * w2.x + xv.w * w3.x;
                acc1 += xv.x * w0.y + xv.y * w1.y + xv.z * w2.y + xv.w * w3.y;
                acc2 += xv.x * w0.z + xv.y * w1.z + xv.z * w2.z + xv.w * w3.z;
                acc3 += xv.x * w0.w + xv.y * w1.w + xv.z * w2.w + xv.w * w3.w;
            }
            acc0 += __ldg(bg + q * 4 + 0);
            acc1 += __ldg(bg + q * 4 + 1);
            acc2 += __ldg(bg + q * 4 + 2);
            acc3 += __ldg(bg + q * 4 + 3);
            float m = fmaxf(fmaxf(acc0, acc1), fmaxf(acc2, acc3));
            m = fmaxf(m, __shfl_xor_sync(0xFFFFFFFFu, m, 1));
            m = fmaxf(m, __shfl_xor_sync(0xFFFFFFFFu, m, 2));
            float v0 = __expf(acc0 - m), v1 = __expf(acc1 - m);
            float v2 = __expf(acc2 - m), v3 = __expf(acc3 - m);
            float s = v0 + v1 + v2 + v3;
            s += __shfl_xor_sync(0xFFFFFFFFu, s, 1);
            s += __shfl_xor_sync(0xFFFFFFFFu, s, 2);
            float inv = 1.0f / s;
            float4 g = make_float4(v0 * inv, v1 * inv, v2 * inv, v3 * inv);
            *reinterpret_cast<float4*>(
                g_gate + (size_t)(token0 + tok) * EE + q * 4) = g;
        }
        NAMED_BAR(1, 512);     // compute warps only: A + gate ready

        float oacc[2][4][4];
        #pragma unroll
        for (int mi = 0; mi < 2; mi++)
            #pragma unroll
            for (int j = 0; j < 4; j++)
                #pragma unroll
                for (int q = 0; q < 4; q++) oacc[mi][j][q] = 0.0f;

        int ph_f[NBUF];
        #pragma unroll
        for (int i = 0; i < NBUF; i++) ph_f[i] = 0;

        #pragma unroll 1
        for (int e = 0; e < EE; e++) {
            float hacc[2][4][4];
            #pragma unroll
            for (int mi = 0; mi < 2; mi++)
                #pragma unroll
                for (int j = 0; j < 4; j++)
                    #pragma unroll
                    for (int q = 0; q < 4; q++) hacc[mi][j][q] = 0.0f;

            #pragma unroll 1
            for (int kc = 0; kc < 8; kc++) {
                const int c = e * 8 + kc;
                const int buf = c & (NBUF - 1);
                MBAR_WAIT(sbase + MB_FULL(buf), ph_f[buf]);
                ph_f[buf] ^= 1;

                const char* bb = smc + SM_B + buf * SM_B_BUF;
                const char* ab = smc + SM_A + ((wm * 8 + kc) * 4) * 1024;
                #pragma unroll
                for (int ks = 0; ks < 4; ks++) {
                    float4 a0 = *reinterpret_cast<const float4*>(
                        ab + ks * 1024 + lane * 16);
                    float4 a1 = *reinterpret_cast<const float4*>(
                        ab + ks * 1024 + 512 + lane * 16);
                    float4 bl = *reinterpret_cast<const float4*>(
                        bb + ((wn * 4 + ks) * 2) * 512 + lane * 16);
                    float4 bh = *reinterpret_cast<const float4*>(
                        bb + ((wn * 4 + ks) * 2 + 1) * 512 + lane * 16);
                    mma_tf32(hacc[0][0], a0, bl.x, bl.y);
                    mma_tf32(hacc[1][0], a1, bl.x, bl.y);
                    mma_tf32(hacc[0][1], a0, bl.z, bl.w);
                    mma_tf32(hacc[1][1], a1, bl.z, bl.w);
                    mma_tf32(hacc[0][2], a0, bh.x, bh.y);
                    mma_tf32(hacc[1][2], a1, bh.x, bh.y);
                    mma_tf32(hacc[0][3], a0, bh.z, bh.w);
                    mma_tf32(hacc[1][3], a1, bh.z, bh.w);
                }
                if (lane == 0) MBAR_ARRIVE(sbase + MB_EMPTY(buf));
            }

            // epilogue: bias + exact gelu + gate-weighted accumulate
            #pragma unroll
            for (int mi = 0; mi < 2; mi++) {
                int rr = token0 + wm * 32 + mi * 16 + (lane >> 2);
                float g0 = __ldg(g_gate + (size_t)rr * EE + e);
                float g1 = __ldg(g_gate + (size_t)(rr + 8) * EE + e);
                #pragma unroll
                for (int j = 0; j < 4; j++) {
                    int n0 = col0 + wn * 32 + j * 8 + (lane & 3) * 2;
                    float bv0 = __ldg(be + (size_t)e * OO + n0);
                    float bv1 = __ldg(be + (size_t)e * OO + n0 + 1);
                    oacc[mi][j][0] = fmaf(g0, gelu_exact(hacc[mi][j][0] + bv0), oacc[mi][j][0]);
                    oacc[mi][j][1] = fmaf(g0, gelu_exact(hacc[mi][j][1] + bv1), oacc[mi][j][1]);
                    oacc[mi][j][2] = fmaf(g1, gelu_exact(hacc[mi][j][2] + bv0), oacc[mi][j][2]);
                    oacc[mi][j][3] = fmaf(g1, gelu_exact(hacc[mi][j][3] + bv1), oacc[mi][j][3]);
                }
            }
        }

        // ---- store ----
        #pragma unroll
        for (int mi = 0; mi < 2; mi++) {
            int row = token0 + wm * 32 + mi * 16 + (lane >> 2);
            #pragma unroll
            for (int j = 0; j < 4; j++) {
                int n = col0 + wn * 32 + j * 8 + (lane & 3) * 2;
                float2 v0 = make_float2(oacc[mi][j][0], oacc[mi][j][1]);
                float2 v1 = make_float2(oacc[mi][j][2], oacc[mi][j][3]);
                *reinterpret_cast<float2*>(out + (size_t)row * OO + n) = v0;
                *reinterpret_cast<float2*>(out + (size_t)(row + 8) * OO + n) = v1;
            }
        }
    }
}

// ---------------------------------------------------------------------------
// kernel_launch — graph-capturable, allocation-free.
// Inputs: x[4,4096,256] f32, We[16,256,256] f32, be[16,256] f32,
//         Wg[256,16] f32, bg[16] f32. Output: [4,4096,256] f32.
// ---------------------------------------------------------------------------
extern "C" void kernel_launch(void* const* d_in, const int* in_sizes, int n_in,
                              void* d_out, int out_size) {
    const float* x  = (const float*)d_in[0];
    const float* We = (const float*)d_in[1];
    const float* be = (const float*)d_in[2];
    const float* Wg = (const float*)d_in[3];
    const float* bg = (const float*)d_in[4];
    float* out = (float*)d_out;

    cudaFuncSetAttribute(moe_kernel,
                         cudaFuncAttributeMaxDynamicSharedMemorySize, SMEM_TOTAL);

    permute_we<<<1024, 256>>>(We);
    moe_kernel<<<(NTOK / TILE_M) * 2, NTHREADS, SMEM_TOTAL>>>(x, be, Wg, bg, out);
}

// round 10
// speedup vs baseline: 1.5562x; 1.3765x over previous
#include <cuda_runtime.h>
#include <cuda_fp16.h>
#include <cstdint>

// ---------------------------------------------------------------------------
// MoE, sm_103: fp16 mma.sync (m16n8k16, fp32 accum) + warp specialization.
//   out[t,o] = sum_e softmax_e(x@Wg+bg)_e * gelu(x@We[e] + be[e])
// B*T=16384, D=256, O=256, E=16.
// fp16 has the same 10-bit mantissa as tf32 -> same rounding error class,
// but 2x MAC/instr and half the smem/L2 bytes.
//
// moe_kernel: CTA = 128 tokens x 128 cols (1 CTA/SM), all 16 experts.
//   18 warps: 16 compute (4Mx4N, warp tile 32x32), 2 producer
//   (cp.async -> 8-stage 8KB mbarrier ring = one full expert of slack).
//   No __syncthreads in the mainloop. Gate softmax fused into prologue.
// ---------------------------------------------------------------------------

#define NTOK   16384
#define DD     256
#define OO     256
#define EE     16
#define TILE_M 128
#define TILE_N 128
#define NTHREADS 576          // 16 compute warps + 2 producer warps
#define NBUF   8

// smem layout (bytes)
#define SM_A      0                      // fp16 A: [wm4][kc8][ks2][mi2][lane32][16B]
#define SM_A_SIZE 65536
#define SM_B      65536                  // 8 x 8KB ring
#define SM_B_BUF  8192
#define SM_BAR    (SM_B + NBUF * SM_B_BUF)   // = 131072
#define MB_FULL(i)  (SM_BAR + (i) * 8)
#define MB_EMPTY(i) (SM_BAR + 64 + (i) * 8)
#define SMEM_TOTAL  (SM_BAR + 160)       // 131232 B -> 1 CTA/SM

// scratch: We as fp16 in m16n8k16 fragment order.
// float4-unit idx bits: e(4)|ct(1)|kc(3)|wn(2)|ks(1)|jp(1)|lane(5)
__device__ uint4 g_WeBh[EE * DD * OO / 8];   // 2 MB
__device__ float g_gate[NTOK * EE];

// ---------------------------------------------------------------------------
__device__ __forceinline__ uint32_t pack_h2(float lo, float hi) {
    __half2 h = __floats2half2_rn(lo, hi);
    return *reinterpret_cast<uint32_t*>(&h);
}
__device__ __forceinline__ uint32_t smem_u32(const void* p) {
    uint32_t a;
    asm("{ .reg .u64 t; cvta.to.shared.u64 t, %1; cvt.u32.u64 %0, t; }"
        : "=r"(a) : "l"(p));
    return a;
}
__device__ __forceinline__ void mma_f16(float* c, const uint4& a,
                                        uint32_t b0, uint32_t b1) {
    asm volatile(
        "mma.sync.aligned.m16n8k16.row.col.f32.f16.f16.f32 "
        "{%0,%1,%2,%3}, {%4,%5,%6,%7}, {%8,%9}, {%0,%1,%2,%3};\n"
        : "+f"(c[0]), "+f"(c[1]), "+f"(c[2]), "+f"(c[3])
        : "r"(a.x), "r"(a.y), "r"(a.z), "r"(a.w), "r"(b0), "r"(b1));
}
__device__ __forceinline__ void cp_async16(uint32_t saddr, const void* gaddr) {
    asm volatile("cp.async.cg.shared.global [%0], [%1], 16;\n"
                 :: "r"(saddr), "l"(gaddr));
}
__device__ __forceinline__ float gelu_exact(float v) {
    return 0.5f * v * (1.0f + erff(v * 0.70710678118654752440f));
}

#define MBAR_INIT(a, n) \
    asm volatile("mbarrier.init.shared.b64 [%0], %1;" :: "r"(a), "r"((uint32_t)(n)) : "memory")
#define MBAR_ARRIVE(a) \
    asm volatile("mbarrier.arrive.shared.b64 _, [%0];" :: "r"(a) : "memory")
#define MBAR_WAIT(a, ph) do {                                                 \
    asm volatile("{\n\t.reg .pred P1;\n\t"                                    \
        "WL_%=:\n\tmbarrier.try_wait.parity.acquire.cta.shared::cta.b64 P1, [%0], %1, 0x989680;\n\t" \
        "@P1 bra.uni WD_%=;\n\tbra.uni WL_%=;\n\tWD_%=:\n\t}"                 \
        :: "r"(a), "r"((uint32_t)(ph)) : "memory");                           \
} while (0)
#define CP_ARRIVE_NOINC(a) \
    asm volatile("cp.async.mbarrier.arrive.noinc.shared::cta.b64 [%0];" :: "r"(a) : "memory")
#define NAMED_BAR(id, n) \
    asm volatile("bar.sync %0, %1;" :: "r"(id), "r"(n) : "memory")

// ---------------------------------------------------------------------------
// Pre-pass: We[e][d][o] -> fp16 m16n8k16 fragment order.
// Per 16B unit (8 halves): two B fragments (n and n+8):
//   {W[k0][n],W[k0+1][n]} {W[k0+8][n],W[k0+9][n]}
//   {W[k0][n+8],W[k0+1][n+8]} {W[k0+8][n+8],W[k0+9][n+8]}
// ---------------------------------------------------------------------------
__global__ void permute_we(const float* __restrict__ We) {
    int idx = blockIdx.x * blockDim.x + threadIdx.x;   // 0 .. 131071
    int lane = idx & 31;
    int jp   = (idx >> 5) & 1;
    int ks   = (idx >> 6) & 1;
    int wn   = (idx >> 7) & 3;
    int kc   = (idx >> 9) & 7;
    int ct   = (idx >> 12) & 1;
    int e    = idx >> 13;
    int g = lane >> 2, t = lane & 3;
    int k0 = kc * 32 + ks * 16 + 2 * t;
    int nA = ct * 128 + wn * 32 + jp * 16 + g;
    const float* w = We + (size_t)e * DD * OO;
    uint4 v;
    v.x = pack_h2(w[(size_t)k0 * OO + nA],       w[(size_t)(k0 + 1) * OO + nA]);
    v.y = pack_h2(w[(size_t)(k0 + 8) * OO + nA], w[(size_t)(k0 + 9) * OO + nA]);
    v.z = pack_h2(w[(size_t)k0 * OO + nA + 8],       w[(size_t)(k0 + 1) * OO + nA + 8]);
    v.w = pack_h2(w[(size_t)(k0 + 8) * OO + nA + 8], w[(size_t)(k0 + 9) * OO + nA + 8]);
    g_WeBh[idx] = v;
}

// ---------------------------------------------------------------------------
// Main kernel: 1 CTA/SM, 128x128 tile.
// ---------------------------------------------------------------------------
__global__ __launch_bounds__(NTHREADS, 1)
void moe_kernel(const float* __restrict__ x, const float* __restrict__ be,
                const float* __restrict__ Wg, const float* __restrict__ bg,
                float* __restrict__ out) {
    extern __shared__ float smf[];
    char* smc = reinterpret_cast<char*>(smf);
    const uint32_t sbase = smem_u32(smc);
    const int tid  = threadIdx.x;
    const int wid  = tid >> 5;
    const int lane = tid & 31;
    const int token0 = (blockIdx.x >> 1) * TILE_M;
    const int ct     = blockIdx.x & 1;
    const int col0   = ct * TILE_N;

    if (tid == 0) {
        #pragma unroll
        for (int i = 0; i < NBUF; i++) {
            MBAR_INIT(sbase + MB_FULL(i), 64);   // 64 producer threads, noinc
            MBAR_INIT(sbase + MB_EMPTY(i), 16);  // one arrive per compute warp
        }
    }
    __syncthreads();

    if (wid >= 16) {
        // ================= producer warps (2 x 32 threads) =================
        const int ltid = tid - 512;              // 0..63
        int ph_e[NBUF];
        #pragma unroll
        for (int i = 0; i < NBUF; i++) ph_e[i] = 0;
        #pragma unroll 1
        for (int c = 0; c < EE * 8; c++) {
            const int buf = c & (NBUF - 1);
            if (c >= NBUF) {
                MBAR_WAIT(sbase + MB_EMPTY(buf), ph_e[buf]);
                ph_e[buf] ^= 1;
            }
            const int e = c >> 3, kc = c & 7;
            const char* gsrc = reinterpret_cast<const char*>(g_WeBh)
                             + (size_t)(e * 16 + ct * 8 + kc) * 8192 + ltid * 16;
            const uint32_t dst = sbase + SM_B + (uint32_t)buf * SM_B_BUF
                               + (uint32_t)ltid * 16;
            #pragma unroll
            for (int i = 0; i < 8; i++)
                cp_async16(dst + i * 1024, gsrc + i * 1024);
            CP_ARRIVE_NOINC(sbase + MB_FULL(buf));
        }
    } else {
        // ================= compute warps (16 x 32 threads) =================
        const int wm = wid & 3;          // 4 row groups of 32 tokens
        const int wn = wid >> 2;         // 4 col groups of 32 cols

        // ---- build A (fp16 fragment order): 4096 16B slots --------------
        {
            #pragma unroll
            for (int it = 0; it < 8; it++) {
                int idx = tid + (it << 9);         // tid 0..511
                int ln = idx & 31;
                int mi = (idx >> 5) & 1;
                int ks = (idx >> 6) & 1;
                int kc = (idx >> 7) & 7;
                int wmm = idx >> 10;               // 0..3
                int g = ln >> 2, t = ln & 3;
                int r0 = token0 + wmm * 32 + mi * 16 + g;
                int c0 = kc * 32 + ks * 16 + 2 * t;
                const float* xp = x + (size_t)r0 * DD + c0;
                float2 p00 = *reinterpret_cast<const float2*>(xp);
                float2 p10 = *reinterpret_cast<const float2*>(xp + 8 * DD);
                float2 p01 = *reinterpret_cast<const float2*>(xp + 8);
                float2 p11 = *reinterpret_cast<const float2*>(xp + 8 * DD + 8);
                uint4 v;
                v.x = pack_h2(p00.x, p00.y);   // a0: row g,   k 2t,2t+1
                v.y = pack_h2(p10.x, p10.y);   // a1: row g+8
                v.z = pack_h2(p01.x, p01.y);   // a2: row g,   k 2t+8,2t+9
                v.w = pack_h2(p11.x, p11.y);   // a3: row g+8
                *reinterpret_cast<uint4*>(smc + SM_A + (size_t)idx * 16) = v;
            }
        }
        // ---- gate: softmax(x@Wg+bg). 4 threads/token, 4 experts each ----
        {
            const int tok = tid >> 2;          // 0..127
            const int q   = tid & 3;
            float acc0 = 0.f, acc1 = 0.f, acc2 = 0.f, acc3 = 0.f;
            const float4* x4 = reinterpret_cast<const float4*>(
                x + (size_t)(token0 + tok) * DD);
            const float4* wg4 = reinterpret_cast<const float4*>(Wg);
            #pragma unroll 4
            for (int d4 = 0; d4 < 64; d4++) {
                float4 xv = x4[d4];
                float4 w0 = wg4[(d4 * 4 + 0) * 4 + q];
                float4 w1 = wg4[(d4 * 4 + 1) * 4 + q];
                float4 w2 = wg4[(d4 * 4 + 2) * 4 + q];
                float4 w3 = wg4[(d4 * 4 + 3) * 4 + q];
                acc0 += xv.x * w0.x + xv.y * w1.x + xv.z * w2.x + xv.w * w3.x;
                acc1 += xv.x * w0.y + xv.y * w1.y + xv.z * w2.y + xv.w * w3.y;
                acc2 += xv.x * w0.z + xv.y * w1.z + xv.z * w2.z + xv.w * w3.z;
                acc3 += xv.x * w0.w + xv.y * w1.w + xv.z * w2.w + xv.w * w3.w;
            }
            acc0 += __ldg(bg + q * 4 + 0);
            acc1 += __ldg(bg + q * 4 + 1);
            acc2 += __ldg(bg + q * 4 + 2);
            acc3 += __ldg(bg + q * 4 + 3);
            float m = fmaxf(fmaxf(acc0, acc1), fmaxf(acc2, acc3));
            m = fmaxf(m, __shfl_xor_sync(0xFFFFFFFFu, m, 1));
            m = fmaxf(m, __shfl_xor_sync(0xFFFFFFFFu, m, 2));
            float v0 = __expf(acc0 - m), v1 = __expf(acc1 - m);
            float v2 = __expf(acc2 - m), v3 = __expf(acc3 - m);
            float s = v0 + v1 + v2 + v3;
            s += __shfl_xor_sync(0xFFFFFFFFu, s, 1);
            s += __shfl_xor_sync(0xFFFFFFFFu, s, 2);
            float inv = 1.0f / s;
            float4 g = make_float4(v0 * inv, v1 * inv, v2 * inv, v3 * inv);
            *reinterpret_cast<float4*>(
                g_gate + (size_t)(token0 + tok) * EE + q * 4) = g;
        }
        NAMED_BAR(1, 512);     // compute warps only: A + gate ready

        float oacc[2][4][4];
        #pragma unroll
        for (int mi = 0; mi < 2; mi++)
            #pragma unroll
            for (int j = 0; j < 4; j++)
                #pragma unroll
                for (int q = 0; q < 4; q++) oacc[mi][j][q] = 0.0f;

        int ph_f[NBUF];
        #pragma unroll
        for (int i = 0; i < NBUF; i++) ph_f[i] = 0;

        #pragma unroll 1
        for (int e = 0; e < EE; e++) {
            float hacc[2][4][4];
            #pragma unroll
            for (int mi = 0; mi < 2; mi++)
                #pragma unroll
                for (int j = 0; j < 4; j++)
                    #pragma unroll
                    for (int q = 0; q < 4; q++) hacc[mi][j][q] = 0.0f;

            #pragma unroll 1
            for (int kc = 0; kc < 8; kc++) {
                const int c = e * 8 + kc;
                const int buf = c & (NBUF - 1);
                MBAR_WAIT(sbase + MB_FULL(buf), ph_f[buf]);
                ph_f[buf] ^= 1;

                const char* bb = smc + SM_B + buf * SM_B_BUF;
                const char* ab = smc + SM_A + (wm * 8 + kc) * 2048 + lane * 16;
                #pragma unroll
                for (int ks = 0; ks < 2; ks++) {
                    uint4 A0 = *reinterpret_cast<const uint4*>(ab + ks * 1024);
                    uint4 A1 = *reinterpret_cast<const uint4*>(ab + ks * 1024 + 512);
                    const char* bp = bb + (wn * 2 + ks) * 1024 + lane * 16;
                    uint4 B0 = *reinterpret_cast<const uint4*>(bp);
                    uint4 B1 = *reinterpret_cast<const uint4*>(bp + 512);
                    mma_f16(hacc[0][0], A0, B0.x, B0.y);
                    mma_f16(hacc[1][0], A1, B0.x, B0.y);
                    mma_f16(hacc[0][1], A0, B0.z, B0.w);
                    mma_f16(hacc[1][1], A1, B0.z, B0.w);
                    mma_f16(hacc[0][2], A0, B1.x, B1.y);
                    mma_f16(hacc[1][2], A1, B1.x, B1.y);
                    mma_f16(hacc[0][3], A0, B1.z, B1.w);
                    mma_f16(hacc[1][3], A1, B1.z, B1.w);
                }
                if (lane == 0) MBAR_ARRIVE(sbase + MB_EMPTY(buf));
            }

            // epilogue: bias + exact gelu + gate-weighted accumulate
            #pragma unroll
            for (int mi = 0; mi < 2; mi++) {
                int rr = token0 + wm * 32 + mi * 16 + (lane >> 2);
                float g0 = __ldg(g_gate + (size_t)rr * EE + e);
                float g1 = __ldg(g_gate + (size_t)(rr + 8) * EE + e);
                #pragma unroll
                for (int j = 0; j < 4; j++) {
                    int n0 = col0 + wn * 32 + j * 8 + (lane & 3) * 2;
                    float bv0 = __ldg(be + (size_t)e * OO + n0);
                    float bv1 = __ldg(be + (size_t)e * OO + n0 + 1);
                    oacc[mi][j][0] = fmaf(g0, gelu_exact(hacc[mi][j][0] + bv0), oacc[mi][j][0]);
                    oacc[mi][j][1] = fmaf(g0, gelu_exact(hacc[mi][j][1] + bv1), oacc[mi][j][1]);
                    oacc[mi][j][2] = fmaf(g1, gelu_exact(hacc[mi][j][2] + bv0), oacc[mi][j][2]);
                    oacc[mi][j][3] = fmaf(g1, gelu_exact(hacc[mi][j][3] + bv1), oacc[mi][j][3]);
                }
            }
        }

        // ---- store ----
        #pragma unroll
        for (int mi = 0; mi < 2; mi++) {
            int row = token0 + wm * 32 + mi * 16 + (lane >> 2);
            #pragma unroll
            for (int j = 0; j < 4; j++) {
                int n = col0 + wn * 32 + j * 8 + (lane & 3) * 2;
                float2 v0 = make_float2(oacc[mi][j][0], oacc[mi][j][1]);
                float2 v1 = make_float2(oacc[mi][j][2], oacc[mi][j][3]);
                *reinterpret_cast<float2*>(out + (size_t)row * OO + n) = v0;
                *reinterpret_cast<float2*>(out + (size_t)(row + 8) * OO + n) = v1;
            }
        }
    }
}

// ---------------------------------------------------------------------------
// kernel_launch — graph-capturable, allocation-free.
// Inputs: x[4,4096,256] f32, We[16,256,256] f32, be[16,256] f32,
//         Wg[256,16] f32, bg[16] f32. Output: [4,4096,256] f32.
// ---------------------------------------------------------------------------
extern "C" void kernel_launch(void* const* d_in, const int* in_sizes, int n_in,
                              void* d_out, int out_size) {
    const float* x  = (const float*)d_in[0];
    const float* We = (const float*)d_in[1];
    const float* be = (const float*)d_in[2];
    const float* Wg = (const float*)d_in[3];
    const float* bg = (const float*)d_in[4];
    float* out = (float*)d_out;

    cudaFuncSetAttribute(moe_kernel,
                         cudaFuncAttributeMaxDynamicSharedMemorySize, SMEM_TOTAL);

    permute_we<<<512, 256>>>(We);
    moe_kernel<<<(NTOK / TILE_M) * 2, NTHREADS, SMEM_TOTAL>>>(x, be, Wg, bg, out);
}

// round 11
// speedup vs baseline: 1.8292x; 1.1754x over previous
#include <cuda_runtime.h>
#include <cuda_fp16.h>
#include <cstdint>

// ---------------------------------------------------------------------------
// MoE, sm_103: fp16 mma.sync (m16n8k16, fp32 accum) + warp specialization.
//   out[t,o] = sum_e softmax_e(x@Wg+bg)_e * gelu(x@We[e] + be[e])
// B*T=16384, D=256, O=256, E=16.
//
// moe_kernel: CTA = 128 tokens x 128 cols (1 CTA/SM), all 16 experts.
//   18 warps: 16 compute (4Mx4N, warp tile 32x32), 2 producer.
//   Ring = 2 buffers x 64KB (one FULL EXPERT each): one mbarrier wait per
//   expert, wait-free 8-chunk inner loop. Branchless A&S-erf GELU epilogue.
// ---------------------------------------------------------------------------

#define NTOK   16384
#define DD     256
#define OO     256
#define EE     16
#define TILE_M 128
#define TILE_N 128
#define NTHREADS 576          // 16 compute warps + 2 producer warps
#define NBUF   2              // expert-granular double buffer

// smem layout (bytes)
#define SM_A      0                      // fp16 A: [wm4][kc8][ks2][mi2][lane32][16B]
#define SM_A_SIZE 65536
#define SM_B      65536                  // 2 x 64KB expert buffers
#define SM_B_BUF  65536
#define SM_BAR    (SM_B + NBUF * SM_B_BUF)   // = 196608
#define MB_FULL(i)  (SM_BAR + (i) * 8)
#define MB_EMPTY(i) (SM_BAR + 16 + (i) * 8)
#define SMEM_TOTAL  (SM_BAR + 64)        // 196672 B -> 1 CTA/SM

// scratch: We as fp16 in m16n8k16 fragment order.
// float4-unit idx bits: e(4)|ct(1)|kc(3)|wn(2)|ks(1)|jp(1)|lane(5)
__device__ uint4 g_WeBh[EE * DD * OO / 8];   // 2 MB
__device__ float g_gate[NTOK * EE];

// ---------------------------------------------------------------------------
__device__ __forceinline__ uint32_t pack_h2(float lo, float hi) {
    __half2 h = __floats2half2_rn(lo, hi);
    return *reinterpret_cast<uint32_t*>(&h);
}
__device__ __forceinline__ uint32_t smem_u32(const void* p) {
    uint32_t a;
    asm("{ .reg .u64 t; cvta.to.shared.u64 t, %1; cvt.u32.u64 %0, t; }"
        : "=r"(a) : "l"(p));
    return a;
}
__device__ __forceinline__ void mma_f16(float* c, const uint4& a,
                                        uint32_t b0, uint32_t b1) {
    asm volatile(
        "mma.sync.aligned.m16n8k16.row.col.f32.f16.f16.f32 "
        "{%0,%1,%2,%3}, {%4,%5,%6,%7}, {%8,%9}, {%0,%1,%2,%3};\n"
        : "+f"(c[0]), "+f"(c[1]), "+f"(c[2]), "+f"(c[3])
        : "r"(a.x), "r"(a.y), "r"(a.z), "r"(a.w), "r"(b0), "r"(b1));
}
__device__ __forceinline__ void cp_async16(uint32_t saddr, const void* gaddr) {
    asm volatile("cp.async.cg.shared.global [%0], [%1], 16;\n"
                 :: "r"(saddr), "l"(gaddr));
}

// Branchless GELU: 0.5*v*(1+erf(v/sqrt2)), erf via A&S 7.1.26 (|err|<=1.5e-7).
// 2 MUFU (rcp, ex2) + ~9 FMA, no branches, no divergence.
__device__ __forceinline__ float gelu_fast(float v) {
    float z = fabsf(v) * 0.70710678118654752f;
    float t = __fdividef(1.0f, fmaf(0.3275911f, z, 1.0f));
    float p = fmaf(t, 1.061405429f, -1.453152027f);
    p = fmaf(t, p, 1.421413741f);
    p = fmaf(t, p, -0.284496736f);
    p = fmaf(t, p, 0.254829592f);
    p = p * t;
    float e  = __expf(-z * z);
    float er = fmaf(-p, e, 1.0f);           // erf(z), z>=0
    er = copysignf(er, v);
    float hv = 0.5f * v;
    return fmaf(hv, er, hv);
}

#define MBAR_INIT(a, n) \
    asm volatile("mbarrier.init.shared.b64 [%0], %1;" :: "r"(a), "r"((uint32_t)(n)) : "memory")
#define MBAR_ARRIVE(a) \
    asm volatile("mbarrier.arrive.shared.b64 _, [%0];" :: "r"(a) : "memory")
#define MBAR_WAIT(a, ph) do {                                                 \
    asm volatile("{\n\t.reg .pred P1;\n\t"                                    \
        "WL_%=:\n\tmbarrier.try_wait.parity.acquire.cta.shared::cta.b64 P1, [%0], %1, 0x989680;\n\t" \
        "@P1 bra.uni WD_%=;\n\tbra.uni WL_%=;\n\tWD_%=:\n\t}"                 \
        :: "r"(a), "r"((uint32_t)(ph)) : "memory");                           \
} while (0)
#define CP_ARRIVE_NOINC(a) \
    asm volatile("cp.async.mbarrier.arrive.noinc.shared::cta.b64 [%0];" :: "r"(a) : "memory")
#define NAMED_BAR(id, n) \
    asm volatile("bar.sync %0, %1;" :: "r"(id), "r"(n) : "memory")

// ---------------------------------------------------------------------------
// Pre-pass: We[e][d][o] -> fp16 m16n8k16 fragment order (unchanged from R10).
// ---------------------------------------------------------------------------
__global__ void permute_we(const float* __restrict__ We) {
    int idx = blockIdx.x * blockDim.x + threadIdx.x;   // 0 .. 131071
    int lane = idx & 31;
    int jp   = (idx >> 5) & 1;
    int ks   = (idx >> 6) & 1;
    int wn   = (idx >> 7) & 3;
    int kc   = (idx >> 9) & 7;
    int ct   = (idx >> 12) & 1;
    int e    = idx >> 13;
    int g = lane >> 2, t = lane & 3;
    int k0 = kc * 32 + ks * 16 + 2 * t;
    int nA = ct * 128 + wn * 32 + jp * 16 + g;
    const float* w = We + (size_t)e * DD * OO;
    uint4 v;
    v.x = pack_h2(w[(size_t)k0 * OO + nA],       w[(size_t)(k0 + 1) * OO + nA]);
    v.y = pack_h2(w[(size_t)(k0 + 8) * OO + nA], w[(size_t)(k0 + 9) * OO + nA]);
    v.z = pack_h2(w[(size_t)k0 * OO + nA + 8],       w[(size_t)(k0 + 1) * OO + nA + 8]);
    v.w = pack_h2(w[(size_t)(k0 + 8) * OO + nA + 8], w[(size_t)(k0 + 9) * OO + nA + 8]);
    g_WeBh[idx] = v;
}

// ---------------------------------------------------------------------------
// Main kernel: 1 CTA/SM, 128x128 tile.
// ---------------------------------------------------------------------------
__global__ __launch_bounds__(NTHREADS, 1)
void moe_kernel(const float* __restrict__ x, const float* __restrict__ be,
                const float* __restrict__ Wg, const float* __restrict__ bg,
                float* __restrict__ out) {
    extern __shared__ float smf[];
    char* smc = reinterpret_cast<char*>(smf);
    const uint32_t sbase = smem_u32(smc);
    const int tid  = threadIdx.x;
    const int wid  = tid >> 5;
    const int lane = tid & 31;
    const int token0 = (blockIdx.x >> 1) * TILE_M;
    const int ct     = blockIdx.x & 1;
    const int col0   = ct * TILE_N;

    if (tid == 0) {
        #pragma unroll
        for (int i = 0; i < NBUF; i++) {
            MBAR_INIT(sbase + MB_FULL(i), 64);   // 64 producer threads, noinc
            MBAR_INIT(sbase + MB_EMPTY(i), 16);  // one arrive per compute warp
        }
    }
    __syncthreads();

    if (wid >= 16) {
        // ========== producer warps: one full expert (64KB) per commit ======
        const int ltid = tid - 512;              // 0..63
        int ph_e[NBUF] = {0, 0};
        #pragma unroll 1
        for (int e = 0; e < EE; e++) {
            const int buf = e & 1;
            if (e >= NBUF) {
                MBAR_WAIT(sbase + MB_EMPTY(buf), ph_e[buf]);
                ph_e[buf] ^= 1;
            }
            const char* gsrc = reinterpret_cast<const char*>(g_WeBh)
                             + (size_t)(e * 2 + ct) * 65536 + ltid * 16;
            const uint32_t dst = sbase + SM_B + (uint32_t)buf * SM_B_BUF
                               + (uint32_t)ltid * 16;
            #pragma unroll
            for (int i = 0; i < 64; i++)
                cp_async16(dst + i * 1024, gsrc + i * 1024);
            CP_ARRIVE_NOINC(sbase + MB_FULL(buf));
        }
    } else {
        // ================= compute warps (16 x 32 threads) =================
        const int wm = wid & 3;          // 4 row groups of 32 tokens
        const int wn = wid >> 2;         // 4 col groups of 32 cols

        // ---- build A (fp16 fragment order): 4096 16B slots --------------
        {
            #pragma unroll
            for (int it = 0; it < 8; it++) {
                int idx = tid + (it << 9);         // tid 0..511
                int ln = idx & 31;
                int mi = (idx >> 5) & 1;
                int ks = (idx >> 6) & 1;
                int kc = (idx >> 7) & 7;
                int wmm = idx >> 10;               // 0..3
                int g = ln >> 2, t = ln & 3;
                int r0 = token0 + wmm * 32 + mi * 16 + g;
                int c0 = kc * 32 + ks * 16 + 2 * t;
                const float* xp = x + (size_t)r0 * DD + c0;
                float2 p00 = *reinterpret_cast<const float2*>(xp);
                float2 p10 = *reinterpret_cast<const float2*>(xp + 8 * DD);
                float2 p01 = *reinterpret_cast<const float2*>(xp + 8);
                float2 p11 = *reinterpret_cast<const float2*>(xp + 8 * DD + 8);
                uint4 v;
                v.x = pack_h2(p00.x, p00.y);
                v.y = pack_h2(p10.x, p10.y);
                v.z = pack_h2(p01.x, p01.y);
                v.w = pack_h2(p11.x, p11.y);
                *reinterpret_cast<uint4*>(smc + SM_A + (size_t)idx * 16) = v;
            }
        }
        // ---- gate: softmax(x@Wg+bg). 4 threads/token, 4 experts each ----
        {
            const int tok = tid >> 2;          // 0..127
            const int q   = tid & 3;
            float acc0 = 0.f, acc1 = 0.f, acc2 = 0.f, acc3 = 0.f;
            const float4* x4 = reinterpret_cast<const float4*>(
                x + (size_t)(token0 + tok) * DD);
            const float4* wg4 = reinterpret_cast<const float4*>(Wg);
            #pragma unroll 4
            for (int d4 = 0; d4 < 64; d4++) {
                float4 xv = x4[d4];
                float4 w0 = wg4[(d4 * 4 + 0) * 4 + q];
                float4 w1 = wg4[(d4 * 4 + 1) * 4 + q];
                float4 w2 = wg4[(d4 * 4 + 2) * 4 + q];
                float4 w3 = wg4[(d4 * 4 + 3) * 4 + q];
                acc0 += xv.x * w0.x + xv.y * w1.x + xv.z * w2.x + xv.w * w3.x;
                acc1 += xv.x * w0.y + xv.y * w1.y + xv.z * w2.y + xv.w * w3.y;
                acc2 += xv.x * w0.z + xv.y * w1.z + xv.z * w2.z + xv.w * w3.z;
                acc3 += xv.x * w0.w + xv.y * w1.w + xv.z * w2.w + xv.w * w3.w;
            }
            acc0 += __ldg(bg + q * 4 + 0);
            acc1 += __ldg(bg + q * 4 + 1);
            acc2 += __ldg(bg + q * 4 + 2);
            acc3 += __ldg(bg + q * 4 + 3);
            float m = fmaxf(fmaxf(acc0, acc1), fmaxf(acc2, acc3));
            m = fmaxf(m, __shfl_xor_sync(0xFFFFFFFFu, m, 1));
            m = fmaxf(m, __shfl_xor_sync(0xFFFFFFFFu, m, 2));
            float v0 = __expf(acc0 - m), v1 = __expf(acc1 - m);
            float v2 = __expf(acc2 - m), v3 = __expf(acc3 - m);
            float s = v0 + v1 + v2 + v3;
            s += __shfl_xor_sync(0xFFFFFFFFu, s, 1);
            s += __shfl_xor_sync(0xFFFFFFFFu, s, 2);
            float inv = 1.0f / s;
            float4 g = make_float4(v0 * inv, v1 * inv, v2 * inv, v3 * inv);
            *reinterpret_cast<float4*>(
                g_gate + (size_t)(token0 + tok) * EE + q * 4) = g;
        }
        NAMED_BAR(1, 512);     // compute warps only: A + gate ready

        float oacc[2][4][4];
        #pragma unroll
        for (int mi = 0; mi < 2; mi++)
            #pragma unroll
            for (int j = 0; j < 4; j++)
                #pragma unroll
                for (int q = 0; q < 4; q++) oacc[mi][j][q] = 0.0f;

        int ph_f[NBUF] = {0, 0};

        #pragma unroll 1
        for (int e = 0; e < EE; e++) {
            const int buf = e & 1;
            MBAR_WAIT(sbase + MB_FULL(buf), ph_f[buf]);
            ph_f[buf] ^= 1;

            float hacc[2][4][4];
            #pragma unroll
            for (int mi = 0; mi < 2; mi++)
                #pragma unroll
                for (int j = 0; j < 4; j++)
                    #pragma unroll
                    for (int q = 0; q < 4; q++) hacc[mi][j][q] = 0.0f;

            const char* bbuf = smc + SM_B + buf * SM_B_BUF;
            const char* abase = smc + SM_A + wm * 16384 + lane * 16;

            // wait-free inner loop: 8 chunks of pure LDS+MMA
            #pragma unroll 2
            for (int kc = 0; kc < 8; kc++) {
                const char* ab = abase + kc * 2048;
                const char* bp0 = bbuf + kc * 8192 + wn * 2048 + lane * 16;
                #pragma unroll
                for (int ks = 0; ks < 2; ks++) {
                    uint4 A0 = *reinterpret_cast<const uint4*>(ab + ks * 1024);
                    uint4 A1 = *reinterpret_cast<const uint4*>(ab + ks * 1024 + 512);
                    const char* bp = bp0 + ks * 1024;
                    uint4 B0 = *reinterpret_cast<const uint4*>(bp);
                    uint4 B1 = *reinterpret_cast<const uint4*>(bp + 512);
                    mma_f16(hacc[0][0], A0, B0.x, B0.y);
                    mma_f16(hacc[1][0], A1, B0.x, B0.y);
                    mma_f16(hacc[0][1], A0, B0.z, B0.w);
                    mma_f16(hacc[1][1], A1, B0.z, B0.w);
                    mma_f16(hacc[0][2], A0, B1.x, B1.y);
                    mma_f16(hacc[1][2], A1, B1.x, B1.y);
                    mma_f16(hacc[0][3], A0, B1.z, B1.w);
                    mma_f16(hacc[1][3], A1, B1.z, B1.w);
                }
            }
            if (lane == 0) MBAR_ARRIVE(sbase + MB_EMPTY(buf));

            // epilogue: bias + branchless gelu + gate-weighted accumulate
            #pragma unroll
            for (int mi = 0; mi < 2; mi++) {
                int rr = token0 + wm * 32 + mi * 16 + (lane >> 2);
                float g0 = __ldg(g_gate + (size_t)rr * EE + e);
                float g1 = __ldg(g_gate + (size_t)(rr + 8) * EE + e);
                #pragma unroll
                for (int j = 0; j < 4; j++) {
                    int n0 = col0 + wn * 32 + j * 8 + (lane & 3) * 2;
                    float bv0 = __ldg(be + (size_t)e * OO + n0);
                    float bv1 = __ldg(be + (size_t)e * OO + n0 + 1);
                    oacc[mi][j][0] = fmaf(g0, gelu_fast(hacc[mi][j][0] + bv0), oacc[mi][j][0]);
                    oacc[mi][j][1] = fmaf(g0, gelu_fast(hacc[mi][j][1] + bv1), oacc[mi][j][1]);
                    oacc[mi][j][2] = fmaf(g1, gelu_fast(hacc[mi][j][2] + bv0), oacc[mi][j][2]);
                    oacc[mi][j][3] = fmaf(g1, gelu_fast(hacc[mi][j][3] + bv1), oacc[mi][j][3]);
                }
            }
        }

        // ---- store ----
        #pragma unroll
        for (int mi = 0; mi < 2; mi++) {
            int row = token0 + wm * 32 + mi * 16 + (lane >> 2);
            #pragma unroll
            for (int j = 0; j < 4; j++) {
                int n = col0 + wn * 32 + j * 8 + (lane & 3) * 2;
                float2 v0 = make_float2(oacc[mi][j][0], oacc[mi][j][1]);
                float2 v1 = make_float2(oacc[mi][j][2], oacc[mi][j][3]);
                *reinterpret_cast<float2*>(out + (size_t)row * OO + n) = v0;
                *reinterpret_cast<float2*>(out + (size_t)(row + 8) * OO + n) = v1;
            }
        }
    }
}

// ---------------------------------------------------------------------------
// kernel_launch — graph-capturable, allocation-free.
// Inputs: x[4,4096,256] f32, We[16,256,256] f32, be[16,256] f32,
//         Wg[256,16] f32, bg[16] f32. Output: [4,4096,256] f32.
// ---------------------------------------------------------------------------
extern "C" void kernel_launch(void* const* d_in, const int* in_sizes, int n_in,
                              void* d_out, int out_size) {
    const float* x  = (const float*)d_in[0];
    const float* We = (const float*)d_in[1];
    const float* be = (const float*)d_in[2];
    const float* Wg = (const float*)d_in[3];
    const float* bg = (const float*)d_in[4];
    float* out = (float*)d_out;

    cudaFuncSetAttribute(moe_kernel,
                         cudaFuncAttributeMaxDynamicSharedMemorySize, SMEM_TOTAL);

    permute_we<<<512, 256>>>(We);
    moe_kernel<<<(NTOK / TILE_M) * 2, NTHREADS, SMEM_TOTAL>>>(x, be, Wg, bg, out);
}